// round 12
// baseline (speedup 1.0000x reference)
#include <cuda_runtime.h>
#include <cuda_fp16.h>
typedef unsigned int u32;

#define HH 56
#define WW 56
#define HW 3136
#define NCTA 128
#define NTPC 7            // tiles per CTA (896/128)
#define TOT  (NTPC*64)

#define SM_CW 64
#define SM_A  3712
#define SM_T  12416
#define SM_B  73728
#define SM_TOTAL 204800
#define TSLAB 7540        // floats per T slab (58*130)

__device__ __align__(16) u32   g_wU[64 * 8192];   // [stage][kp64][n128] fp16x2 swizzled
__device__ __align__(16) float g_cw[4 * HW];
__device__ const float CAF[2][4] = {{1.f, 1.f, 1.f, 0.f}, {0.f, 1.f, -1.f, -1.f}};

__device__ __forceinline__ u32 smem_u32(const void* p) {
    u32 a;
    asm("{ .reg .u64 t; cvta.to.shared.u64 t, %1; cvt.u32.u64 %0, t; }" : "=r"(a) : "l"(p));
    return a;
}
__device__ __forceinline__ u32 pack_h2(float lo, float hi) {
    __half2 h = __floats2half2_rn(lo, hi);
    return *(u32*)&h;
}
__device__ __forceinline__ void mbar_init(u32 a, u32 c) {
    asm volatile("mbarrier.init.shared.b64 [%0], %1;" :: "r"(a), "r"(c) : "memory");
}
__device__ __forceinline__ void mbar_expect_tx(u32 a, u32 b) {
    asm volatile("mbarrier.arrive.expect_tx.shared.b64 _, [%0], %1;" :: "r"(a), "r"(b) : "memory");
}
__device__ __forceinline__ void mbar_wait(u32 a, int ph) {
    asm volatile(
        "{\n\t.reg .pred P;\n"
        "WL_%=:\n\t"
        "mbarrier.try_wait.parity.acquire.cta.shared::cta.b64 P, [%0], %1, 0x989680;\n\t"
        "@P bra.uni WD_%=;\n\t"
        "bra.uni WL_%=;\n\t"
        "WD_%=:\n\t}" :: "r"(a), "r"((u32)ph) : "memory");
}
__device__ __forceinline__ void bulk_copy(u32 d, const void* s, u32 b, u32 m) {
    asm volatile(
        "cp.async.bulk.shared::cluster.global.mbarrier::complete_tx::bytes [%0], [%1], %2, [%3];"
        :: "r"(d), "l"(s), "r"(b), "r"(m) : "memory");
}
__device__ __forceinline__ void mma_f16(float& d0, float& d1, float& d2, float& d3,
                                        u32 a0, u32 a1, u32 a2, u32 a3, u32 b0, u32 b1) {
    asm volatile(
        "mma.sync.aligned.m16n8k16.row.col.f32.f16.f16.f32 "
        "{%0,%1,%2,%3}, {%4,%5,%6,%7}, {%8,%9}, {%0,%1,%2,%3};"
        : "+f"(d0), "+f"(d1), "+f"(d2), "+f"(d3)
        : "r"(a0), "r"(a1), "r"(a2), "r"(a3), "r"(b0), "r"(b1));
}

__global__ void prep_cw_kernel(const float* __restrict__ cw_row,
                               const float* __restrict__ cw_col) {
    int idx = blockIdx.x * blockDim.x + threadIdx.x;
    if (idx >= HW) return;
    int y = idx / WW, x = idx % WW;
    float v0 = cw_row[y] + cw_col[x];
    float v1 = cw_row[HH + y] + cw_col[WW + x];
    float v2 = cw_row[2 * HH + y] + cw_col[2 * WW + x];
    float v3 = cw_row[3 * HH + y] + cw_col[3 * WW + x];
    float m = fmaxf(fmaxf(v0, v1), fmaxf(v2, v3));
    float e0 = expf(v0 - m), e1 = expf(v1 - m), e2 = expf(v2 - m), e3 = expf(v3 - m);
    float inv = 1.0f / (e0 + e1 + e2 + e3);
    g_cw[idx] = e0 * inv; g_cw[HW + idx] = e1 * inv;
    g_cw[2 * HW + idx] = e2 * inv; g_cw[3 * HW + idx] = e3 * inv;
}

__global__ void prep_wU_kernel(const float* __restrict__ w) {
    int idx = blockIdx.x * blockDim.x + threadIdx.x;
    if (idx >= 4 * 128 * 64) return;
    int kp = idx & 63, oc = (idx >> 6) & 127, r = idx >> 13;
    float U[2][4][4];
#pragma unroll
    for (int e2 = 0; e2 < 2; e2++) {
        const float* wb = w + (((size_t)r * 128 + oc) * 128 + 2 * kp + e2) * 9;
        float tm[4][3];
#pragma unroll
        for (int b = 0; b < 3; b++) {
            float w0 = wb[b], w1 = wb[3 + b], w2 = wb[6 + b];
            tm[0][b] = w0; tm[1][b] = 0.5f * (w0 + w1 + w2);
            tm[2][b] = 0.5f * (w0 - w1 + w2); tm[3][b] = w2;
        }
#pragma unroll
        for (int u = 0; u < 4; u++) {
            U[e2][u][0] = tm[u][0];
            U[e2][u][1] = 0.5f * (tm[u][0] + tm[u][1] + tm[u][2]);
            U[e2][u][2] = 0.5f * (tm[u][0] - tm[u][1] + tm[u][2]);
            U[e2][u][3] = tm[u][2];
        }
    }
    int col = oc ^ ((kp & 3) << 3);
#pragma unroll
    for (int u = 0; u < 4; u++)
#pragma unroll
        for (int v = 0; v < 4; v++)
            g_wU[(size_t)((u * 4 + v) * 4 + r) * 8192 + kp * 128 + col] =
                pack_h2(U[0][u][v], U[1][u][v]);
}

// Build 2 items of slab T[up] (column transform B^T d) for tile (bb,y0).
__device__ __forceinline__ void buildT2(float* Ts, const float* __restrict__ x,
                                        int bb, int y0, int up, int s15, int tid) {
    const int dyA[4] = {0, 1, 2, 1}, dyB[4] = {2, 2, 1, 3};
    const float sBt[4] = {-1.f, 1.f, -1.f, -1.f};
#pragma unroll
    for (int j = 0; j < 2; j++) {
        int idx = (s15 * 2 + j) * 256 + tid;
        int tx = idx & 63, kp = idx >> 6;
        if (tx < 58) {
            int gx = tx - 1;
            int gyA = 2 * y0 - 1 + dyA[up], gyB = 2 * y0 - 1 + dyB[up];
            const float* xb = x + ((size_t)bb * 128 + 2 * kp) * HW;
            bool okx = (unsigned)gx < 56u;
            bool okA = okx && (unsigned)gyA < 56u;
            bool okB = okx && (unsigned)gyB < 56u;
            float a0 = okA ? xb[gyA * 56 + gx] : 0.f;
            float a1 = okA ? xb[HW + gyA * 56 + gx] : 0.f;
            float b0 = okB ? xb[gyB * 56 + gx] : 0.f;
            float b1 = okB ? xb[HW + gyB * 56 + gx] : 0.f;
            float sb = sBt[up];
            *(float2*)&Ts[tx * 130 + 2 * kp] = make_float2(a0 + sb * b0, a1 + sb * b1);
        }
    }
}

// Row transform: A_e rows 0..27 from fp32 slab (single fp16 rounding).
__device__ __forceinline__ void buildA(u32* Ab, const float* Tu, int v, int tid) {
#pragma unroll
    for (int it = 0; it < 7; it++) {
        int idx = it * 256 + tid;
        int kp = idx & 63, b = idx >> 6;
        float2 p, q; float sq = -1.f;
        if (v == 0)      { p = *(const float2*)&Tu[(2*b+0)*130+2*kp]; q = *(const float2*)&Tu[(2*b+2)*130+2*kp]; }
        else if (v == 1) { p = *(const float2*)&Tu[(2*b+1)*130+2*kp]; q = *(const float2*)&Tu[(2*b+2)*130+2*kp]; sq = 1.f; }
        else if (v == 2) { p = *(const float2*)&Tu[(2*b+2)*130+2*kp]; q = *(const float2*)&Tu[(2*b+1)*130+2*kp]; }
        else             { p = *(const float2*)&Tu[(2*b+1)*130+2*kp]; q = *(const float2*)&Tu[(2*b+3)*130+2*kp]; }
        Ab[b * 68 + kp] = pack_h2(p.x + sq * q.x, p.y + sq * q.y);
    }
}

// 128 persistent CTAs x 256 thr (8 warps: 2 wm x 4 woc); CTA c: tiles c+128*ti, ti<7.
__global__ __launch_bounds__(256, 1)
void wino_kernel(const float* __restrict__ x, float* __restrict__ out,
                 const float* __restrict__ b_row, const float* __restrict__ b_col,
                 const float* __restrict__ b_ch) {
    extern __shared__ char smem[];
    const u32 sbase = smem_u32(smem);
    const int tid = threadIdx.x, wid = tid >> 5, lane = tid & 31;
    const int wm = wid & 1, woc = wid >> 1;
    const int g = lane >> 2, t = lane & 3;
    const int c = blockIdx.x;

    float* cwb = (float*)(smem + SM_CW);
    u32*   Ab  = (u32*)(smem + SM_A);
    float* Tf  = (float*)(smem + SM_T);

    if (tid == 0)
        for (int i = 0; i < 4; i++) mbar_init(sbase + i * 8, 1);
    __syncthreads();
    if (tid == 0)
        for (int i = 0; i < 4; i++) {
            mbar_expect_tx(sbase + i * 8, 32768);
            bulk_copy(sbase + SM_B + i * 32768, (const char*)g_wU + (size_t)i * 32768,
                      32768, sbase + i * 8);
        }

    // prologue: tile 0 slab0 + cws + A pad + A(e0)
    {
        const int y00 = c % 28, bb0 = c / 28;
        for (int s15 = 0; s15 < 8; s15++) buildT2(Tf, x, bb0, y00, 0, s15, tid);
        for (int idx = tid; idx < 448; idx += 256) {
            int rr = idx / 112, rem = idx % 112;
            cwb[idx] = g_cw[rr * HW + (2 * y00 + rem / 56) * 56 + rem % 56];
        }
        for (int i = 28 * 68 + tid; i < 32 * 68; i += 256) Ab[i] = 0;
        __syncthreads();
        buildA(Ab, Tf, 0, tid);
        __syncthreads();
    }

    float acc[2][2][4][4];
#pragma unroll
    for (int i = 0; i < 2; i++)
#pragma unroll
        for (int j = 0; j < 2; j++)
#pragma unroll
            for (int nt = 0; nt < 4; nt++)
#pragma unroll
                for (int v2 = 0; v2 < 4; v2++) acc[i][j][nt][v2] = 0.f;

    const int ar0 = (wm * 16 + g) * 68, ar1 = ar0 + 8 * 68;

    for (int gs = 0; gs < TOT; gs++) {
        const int s = gs & 63, e = s >> 2, r = s & 3, u = e >> 2, v = e & 3;
        const int ti = gs >> 6;
        mbar_wait(sbase + (gs & 3) * 8, (gs >> 2) & 1);

        float mf[4][4];
#pragma unroll
        for (int nt = 0; nt < 4; nt++)
#pragma unroll
            for (int v2 = 0; v2 < 4; v2++) mf[nt][v2] = 0.f;

        const u32* Bb = (const u32*)(smem + SM_B + (gs & 3) * 32768);
#pragma unroll
        for (int ks = 0; ks < 8; ks++) {
            const int ak = ks * 8 + t;
            u32 a0 = Ab[ar0 + ak], a1 = Ab[ar1 + ak];
            u32 a2 = Ab[ar0 + ak + 4], a3 = Ab[ar1 + ak + 4];
#pragma unroll
            for (int nt = 0; nt < 4; nt++) {
                const int col = (woc * 32 + nt * 8 + g) ^ (t << 3);
                mma_f16(mf[nt][0], mf[nt][1], mf[nt][2], mf[nt][3],
                        a0, a1, a2, a3, Bb[ak * 128 + col], Bb[(ak + 4) * 128 + col]);
            }
        }

        // fold
        {
            const float* cws = cwb + (ti & 1) * 448;
            const float cu0 = CAF[0][u], cu1 = CAF[1][u];
            const float cv0 = CAF[0][v], cv1 = CAF[1][v];
#pragma unroll
            for (int i = 0; i < 2; i++)
#pragma unroll
                for (int j = 0; j < 2; j++) {
                    const float ca = (i ? cu1 : cu0) * (j ? cv1 : cv0);
                    if (ca != 0.f) {
                        const float w0 = ca * cws[r * 112 + i * 56 + 2 * (wm * 16 + g) + j];
                        const float w1 = ca * cws[r * 112 + i * 56 + 2 * (wm * 16 + g + 8) + j];
#pragma unroll
                        for (int nt = 0; nt < 4; nt++) {
                            acc[i][j][nt][0] += w0 * mf[nt][0];
                            acc[i][j][nt][1] += w0 * mf[nt][1];
                            acc[i][j][nt][2] += w1 * mf[nt][2];
                            acc[i][j][nt][3] += w1 * mf[nt][3];
                        }
                    }
                }
        }

        // pipelined slab build (2 items/thread over first 8 stages of each u-block)
        const int s15 = s & 15;
        if (s15 < 8) {
            int upn = u + 1, tin = ti;
            if (upn == 4) { upn = 0; tin = ti + 1; }
            if (tin < NTPC) {
                const int tt = c + tin * NCTA;
                buildT2(Tf + (upn & 1) * TSLAB, x, tt / 28, tt % 28, upn, s15, tid);
            }
        }
        // next tile's combine weights during u==3
        if (u == 3 && (s15 == 8 || s15 == 9) && ti + 1 < NTPC) {
            const int tt = c + (ti + 1) * NCTA;
            const int y0n = tt % 28, bbn = tt / 28; (void)bbn;
            float* cwn = cwb + ((ti + 1) & 1) * 448;
            int idx = (s15 - 8) * 256 + tid;
            if (idx < 448) {
                int rr = idx / 112, rem = idx % 112;
                cwn[idx] = g_cw[rr * HW + (2 * y0n + rem / 56) * 56 + rem % 56];
            }
        }

        __syncthreads();
        if (tid == 0 && gs + 4 < TOT) {
            u32 mb = sbase + (gs & 3) * 8;
            mbar_expect_tx(mb, 32768);
            bulk_copy(sbase + SM_B + (gs & 3) * 32768,
                      (const char*)g_wU + (size_t)((gs + 4) & 63) * 32768, 32768, mb);
        }

        if (r == 3) {
            if (s == 63) {
                // epilogue for tile ti
                const int tt = c + ti * NCTA;
                const int y0 = tt % 28, bb = tt / 28;
                const float br0 = b_row[2 * y0], br1 = b_row[2 * y0 + 1];
#pragma unroll
                for (int i = 0; i < 2; i++)
#pragma unroll
                    for (int j = 0; j < 2; j++)
#pragma unroll
                        for (int nt = 0; nt < 4; nt++)
#pragma unroll
                            for (int v2 = 0; v2 < 4; v2++) {
                                const int b = wm * 16 + g + 8 * (v2 >> 1);
                                if (b < 28) {
                                    const int xx = 2 * b + j, yy = 2 * y0 + i;
                                    const int oc = woc * 32 + nt * 8 + 2 * t + (v2 & 1);
                                    out[((size_t)(bb * 128 + oc) * 56 + yy) * 56 + xx] =
                                        acc[i][j][nt][v2] + (i ? br1 : br0) + b_col[xx] + b_ch[oc];
                                }
                            }
#pragma unroll
                for (int i = 0; i < 2; i++)
#pragma unroll
                    for (int j = 0; j < 2; j++)
#pragma unroll
                        for (int nt = 0; nt < 4; nt++)
#pragma unroll
                            for (int v2 = 0; v2 < 4; v2++) acc[i][j][nt][v2] = 0.f;
                if (ti + 1 < NTPC) buildA(Ab, Tf, 0, tid);
            } else {
                const int e1 = e + 1;
                buildA(Ab, Tf + (((e1 >> 2) & 1) * TSLAB), e1 & 3, tid);
            }
            __syncthreads();
        }
    }
}

extern "C" void kernel_launch(void* const* d_in, const int* in_sizes, int n_in,
                              void* d_out, int out_size) {
    const float* x      = (const float*)d_in[0];
    const float* w      = (const float*)d_in[1];
    const float* cw_row = (const float*)d_in[2];
    const float* cw_col = (const float*)d_in[3];
    const float* b_row  = (const float*)d_in[4];
    const float* b_col  = (const float*)d_in[5];
    const float* b_ch   = (const float*)d_in[6];
    float* out = (float*)d_out;

    cudaFuncSetAttribute(wino_kernel,
                         cudaFuncAttributeMaxDynamicSharedMemorySize, SM_TOTAL);
    prep_cw_kernel<<<(HW + 255) / 256, 256>>>(cw_row, cw_col);
    prep_wU_kernel<<<128, 256>>>(w);
    wino_kernel<<<NCTA, 256, SM_TOTAL>>>(x, out, b_row, b_col, b_ch);
}

// round 15
// speedup vs baseline: 1.9592x; 1.9592x over previous
#include <cuda_runtime.h>
#include <cuda_fp16.h>
typedef unsigned int u32;

#define HH 56
#define WW 56
#define HW 3136
#define TSLAB 7540        // floats per T slab (58*130)

#define SM_CW 64
#define SM_A  1920
#define SM_T  10624
#define SM_B  73728
#define SM_TOTAL 204800   // 4x32KB B ring ends here

__device__ __align__(16) u32   g_wU[64 * 8192];   // [stage][kp64][n128] fp16x2 swizzled
__device__ __align__(16) float g_cw[4 * HW];
__device__ const float CAF[2][4] = {{1.f, 1.f, 1.f, 0.f}, {0.f, 1.f, -1.f, -1.f}};

__device__ __forceinline__ u32 smem_u32(const void* p) {
    u32 a;
    asm("{ .reg .u64 t; cvta.to.shared.u64 t, %1; cvt.u32.u64 %0, t; }" : "=r"(a) : "l"(p));
    return a;
}
__device__ __forceinline__ u32 pack_h2(float lo, float hi) {
    __half2 h = __floats2half2_rn(lo, hi);
    return *(u32*)&h;
}
__device__ __forceinline__ void mbar_init(u32 a, u32 c) {
    asm volatile("mbarrier.init.shared.b64 [%0], %1;" :: "r"(a), "r"(c) : "memory");
}
__device__ __forceinline__ void mbar_expect_tx(u32 a, u32 b) {
    asm volatile("mbarrier.arrive.expect_tx.shared.b64 _, [%0], %1;" :: "r"(a), "r"(b) : "memory");
}
__device__ __forceinline__ void mbar_wait(u32 a, int ph) {
    asm volatile(
        "{\n\t.reg .pred P;\n"
        "WL_%=:\n\t"
        "mbarrier.try_wait.parity.acquire.cta.shared::cta.b64 P, [%0], %1, 0x989680;\n\t"
        "@P bra.uni WD_%=;\n\t"
        "bra.uni WL_%=;\n\t"
        "WD_%=:\n\t}" :: "r"(a), "r"((u32)ph) : "memory");
}
__device__ __forceinline__ void bulk_copy(u32 d, const void* s, u32 b, u32 m) {
    asm volatile(
        "cp.async.bulk.shared::cluster.global.mbarrier::complete_tx::bytes [%0], [%1], %2, [%3];"
        :: "r"(d), "l"(s), "r"(b), "r"(m) : "memory");
}
__device__ __forceinline__ void mma_f16(float& d0, float& d1, float& d2, float& d3,
                                        u32 a0, u32 a1, u32 a2, u32 a3, u32 b0, u32 b1) {
    asm volatile(
        "mma.sync.aligned.m16n8k16.row.col.f32.f16.f16.f32 "
        "{%0,%1,%2,%3}, {%4,%5,%6,%7}, {%8,%9}, {%0,%1,%2,%3};"
        : "+f"(d0), "+f"(d1), "+f"(d2), "+f"(d3)
        : "r"(a0), "r"(a1), "r"(a2), "r"(a3), "r"(b0), "r"(b1));
}

__global__ void prep_cw_kernel(const float* __restrict__ cw_row,
                               const float* __restrict__ cw_col) {
    int idx = blockIdx.x * blockDim.x + threadIdx.x;
    if (idx >= HW) return;
    int y = idx / WW, x = idx % WW;
    float v0 = cw_row[y] + cw_col[x];
    float v1 = cw_row[HH + y] + cw_col[WW + x];
    float v2 = cw_row[2 * HH + y] + cw_col[2 * WW + x];
    float v3 = cw_row[3 * HH + y] + cw_col[3 * WW + x];
    float m = fmaxf(fmaxf(v0, v1), fmaxf(v2, v3));
    float e0 = expf(v0 - m), e1 = expf(v1 - m), e2 = expf(v2 - m), e3 = expf(v3 - m);
    float inv = 1.0f / (e0 + e1 + e2 + e3);
    g_cw[idx] = e0 * inv; g_cw[HW + idx] = e1 * inv;
    g_cw[2 * HW + idx] = e2 * inv; g_cw[3 * HW + idx] = e3 * inv;
}

__global__ void prep_wU_kernel(const float* __restrict__ w) {
    int idx = blockIdx.x * blockDim.x + threadIdx.x;
    if (idx >= 4 * 128 * 64) return;
    int kp = idx & 63, oc = (idx >> 6) & 127, r = idx >> 13;
    float U[2][4][4];
#pragma unroll
    for (int e2 = 0; e2 < 2; e2++) {
        const float* wb = w + (((size_t)r * 128 + oc) * 128 + 2 * kp + e2) * 9;
        float tm[4][3];
#pragma unroll
        for (int b = 0; b < 3; b++) {
            float w0 = wb[b], w1 = wb[3 + b], w2 = wb[6 + b];
            tm[0][b] = w0; tm[1][b] = 0.5f * (w0 + w1 + w2);
            tm[2][b] = 0.5f * (w0 - w1 + w2); tm[3][b] = w2;
        }
#pragma unroll
        for (int u = 0; u < 4; u++) {
            U[e2][u][0] = tm[u][0];
            U[e2][u][1] = 0.5f * (tm[u][0] + tm[u][1] + tm[u][2]);
            U[e2][u][2] = 0.5f * (tm[u][0] - tm[u][1] + tm[u][2]);
            U[e2][u][3] = tm[u][2];
        }
    }
    int col = oc ^ ((kp & 3) << 3);
#pragma unroll
    for (int u = 0; u < 4; u++)
#pragma unroll
        for (int v = 0; v < 4; v++)
            g_wU[(size_t)((u * 4 + v) * 4 + r) * 8192 + kp * 128 + col] =
                pack_h2(U[0][u][v], U[1][u][v]);
}

// split slab build: 2 items/thread; LDG half (issue early, latency hidden)
__device__ __forceinline__ void ldgT2(float* va, const float* __restrict__ x,
                                      int bb, int y0, int up, int s15, int tid, bool en) {
    const int dyA[4] = {0, 1, 2, 1}, dyB[4] = {2, 2, 1, 3};
#pragma unroll
    for (int j = 0; j < 2; j++) {
        int idx = (s15 * 2 + j) * 256 + tid;
        int tx = idx & 63, kp = idx >> 6;
        int gx = tx - 1;
        int gyA = 2 * y0 - 1 + dyA[up & 3], gyB = 2 * y0 - 1 + dyB[up & 3];
        bool okx = en && tx < 58 && (unsigned)gx < 56u;
        bool okA = okx && (unsigned)gyA < 56u;
        bool okB = okx && (unsigned)gyB < 56u;
        const float* xb = x + ((size_t)bb * 128 + 2 * kp) * HW;
        va[4 * j + 0] = okA ? xb[gyA * 56 + gx] : 0.f;
        va[4 * j + 1] = okA ? xb[HW + gyA * 56 + gx] : 0.f;
        va[4 * j + 2] = okB ? xb[gyB * 56 + gx] : 0.f;
        va[4 * j + 3] = okB ? xb[HW + gyB * 56 + gx] : 0.f;
    }
}
// STS half (after MMA block)
__device__ __forceinline__ void stsT2(float* Ts, const float* va, int up, int s15,
                                      int tid, bool en) {
    const float sBt[4] = {-1.f, 1.f, -1.f, -1.f};
    if (!en) return;
    float sb = sBt[up & 3];
#pragma unroll
    for (int j = 0; j < 2; j++) {
        int idx = (s15 * 2 + j) * 256 + tid;
        int tx = idx & 63, kp = idx >> 6;
        if (tx < 58)
            *(float2*)&Ts[tx * 130 + 2 * kp] =
                make_float2(va[4 * j + 0] + sb * va[4 * j + 2],
                            va[4 * j + 1] + sb * va[4 * j + 3]);
    }
}

// Row transform: A_e rows 0..27 from fp32 slab (single fp16 rounding).
__device__ __forceinline__ void buildA(u32* Ab, const float* Tu, int v, int tid) {
#pragma unroll
    for (int it = 0; it < 7; it++) {
        int idx = it * 256 + tid;
        int kp = idx & 63, b = idx >> 6;
        float2 p, q; float sq = -1.f;
        if (v == 0)      { p = *(const float2*)&Tu[(2*b+0)*130+2*kp]; q = *(const float2*)&Tu[(2*b+2)*130+2*kp]; }
        else if (v == 1) { p = *(const float2*)&Tu[(2*b+1)*130+2*kp]; q = *(const float2*)&Tu[(2*b+2)*130+2*kp]; sq = 1.f; }
        else if (v == 2) { p = *(const float2*)&Tu[(2*b+2)*130+2*kp]; q = *(const float2*)&Tu[(2*b+1)*130+2*kp]; }
        else             { p = *(const float2*)&Tu[(2*b+1)*130+2*kp]; q = *(const float2*)&Tu[(2*b+3)*130+2*kp]; }
        Ab[b * 68 + kp] = pack_h2(p.x + sq * q.x, p.y + sq * q.y);
    }
}

// grid (28, 32) = (block-row y0, image). 256 thr = 8 warps (2 wm x 4 woc).
__global__ __launch_bounds__(256, 1)
void wino_kernel(const float* __restrict__ x, float* __restrict__ out,
                 const float* __restrict__ b_row, const float* __restrict__ b_col,
                 const float* __restrict__ b_ch) {
    extern __shared__ char smem[];
    const u32 sbase = smem_u32(smem);
    const int tid = threadIdx.x, wid = tid >> 5, lane = tid & 31;
    const int wm = wid & 1, woc = wid >> 1;
    const int g = lane >> 2, t = lane & 3;
    const int y0 = blockIdx.x, bb = blockIdx.y;

    float* cws = (float*)(smem + SM_CW);
    u32*   Ab  = (u32*)(smem + SM_A);
    float* Tf  = (float*)(smem + SM_T);

    if (tid == 0)
        for (int i = 0; i < 4; i++) mbar_init(sbase + i * 8, 1);
    __syncthreads();
    if (tid == 0)
        for (int i = 0; i < 4; i++) {
            mbar_expect_tx(sbase + i * 8, 32768);
            bulk_copy(sbase + SM_B + i * 32768, (const char*)g_wU + (size_t)i * 32768,
                      32768, sbase + i * 8);
        }

    // prologue: slab 0 only + cws + A pad + A(e0)
    {
        for (int s15 = 0; s15 < 8; s15++) {
            float va[8];
            ldgT2(va, x, bb, y0, 0, s15, tid, true);
            stsT2(Tf, va, 0, s15, tid, true);
        }
        for (int idx = tid; idx < 448; idx += 256) {
            int rr = idx / 112, rem = idx % 112;
            cws[idx] = g_cw[rr * HW + (2 * y0 + rem / 56) * 56 + rem % 56];
        }
        for (int i = 28 * 68 + tid; i < 32 * 68; i += 256) Ab[i] = 0;
        __syncthreads();
        buildA(Ab, Tf, 0, tid);
        __syncthreads();
    }

    float acc[2][2][4][4];
#pragma unroll
    for (int i = 0; i < 2; i++)
#pragma unroll
        for (int j = 0; j < 2; j++)
#pragma unroll
            for (int nt = 0; nt < 4; nt++)
#pragma unroll
                for (int v2 = 0; v2 < 4; v2++) acc[i][j][nt][v2] = 0.f;

    const int ar0 = (wm * 16 + g) * 68, ar1 = ar0 + 8 * 68;

    for (int s = 0; s < 64; s++) {
        const int e = s >> 2, r = s & 3, u = e >> 2, v = e & 3, s15 = s & 15;

        // early LDG for next slab (hidden under wait+MMA)
        float va[8];
        const bool en = (s15 < 8) && (u < 3);
        const int up1 = u + 1;
        ldgT2(va, x, bb, y0, up1, s15, tid, en);

        mbar_wait(sbase + (s & 3) * 8, (s >> 2) & 1);

        float mf[4][4];
#pragma unroll
        for (int nt = 0; nt < 4; nt++)
#pragma unroll
            for (int v2 = 0; v2 < 4; v2++) mf[nt][v2] = 0.f;

        const u32* Bb = (const u32*)(smem + SM_B + (s & 3) * 32768);
#pragma unroll
        for (int ks = 0; ks < 8; ks++) {
            const int ak = ks * 8 + t;
            u32 a0 = Ab[ar0 + ak], a1 = Ab[ar1 + ak];
            u32 a2 = Ab[ar0 + ak + 4], a3 = Ab[ar1 + ak + 4];
#pragma unroll
            for (int nt = 0; nt < 4; nt++) {
                const int col = (woc * 32 + nt * 8 + g) ^ (t << 3);
                mma_f16(mf[nt][0], mf[nt][1], mf[nt][2], mf[nt][3],
                        a0, a1, a2, a3, Bb[ak * 128 + col], Bb[(ak + 4) * 128 + col]);
            }
        }

        // fold: acc += A^T[i][u]*A^T[j][v]*cw_r(px) * mf
        {
            const float cu0 = CAF[0][u], cu1 = CAF[1][u];
            const float cv0 = CAF[0][v], cv1 = CAF[1][v];
#pragma unroll
            for (int i = 0; i < 2; i++)
#pragma unroll
                for (int j = 0; j < 2; j++) {
                    const float ca = (i ? cu1 : cu0) * (j ? cv1 : cv0);
                    if (ca != 0.f) {
                        const float w0 = ca * cws[r * 112 + i * 56 + 2 * (wm * 16 + g) + j];
                        const float w1 = ca * cws[r * 112 + i * 56 + 2 * (wm * 16 + g + 8) + j];
#pragma unroll
                        for (int nt = 0; nt < 4; nt++) {
                            acc[i][j][nt][0] += w0 * mf[nt][0];
                            acc[i][j][nt][1] += w0 * mf[nt][1];
                            acc[i][j][nt][2] += w1 * mf[nt][2];
                            acc[i][j][nt][3] += w1 * mf[nt][3];
                        }
                    }
                }
        }

        // STS half of the slab build
        stsT2(Tf + (up1 & 1) * TSLAB, va, up1, s15, tid, en);

        __syncthreads();
        if (tid == 0 && s + 4 < 64) {
            u32 mb = sbase + (s & 3) * 8;
            mbar_expect_tx(mb, 32768);
            bulk_copy(sbase + SM_B + (s & 3) * 32768,
                      (const char*)g_wU + (size_t)(s + 4) * 32768, 32768, mb);
        }

        if (r == 3 && s < 63) {
            const int e1 = e + 1;
            buildA(Ab, Tf + (((e1 >> 2) & 1) * TSLAB), e1 & 3, tid);
            __syncthreads();
        }
    }

    // epilogue: direct stores + biases
    const float br0 = b_row[2 * y0], br1 = b_row[2 * y0 + 1];
#pragma unroll
    for (int i = 0; i < 2; i++)
#pragma unroll
        for (int j = 0; j < 2; j++)
#pragma unroll
            for (int nt = 0; nt < 4; nt++)
#pragma unroll
                for (int v2 = 0; v2 < 4; v2++) {
                    const int b = wm * 16 + g + 8 * (v2 >> 1);
                    if (b < 28) {
                        const int xx = 2 * b + j, yy = 2 * y0 + i;
                        const int oc = woc * 32 + nt * 8 + 2 * t + (v2 & 1);
                        out[((size_t)(bb * 128 + oc) * 56 + yy) * 56 + xx] =
                            acc[i][j][nt][v2] + (i ? br1 : br0) + b_col[xx] + b_ch[oc];
                    }
                }
}

extern "C" void kernel_launch(void* const* d_in, const int* in_sizes, int n_in,
                              void* d_out, int out_size) {
    const float* x      = (const float*)d_in[0];
    const float* w      = (const float*)d_in[1];
    const float* cw_row = (const float*)d_in[2];
    const float* cw_col = (const float*)d_in[3];
    const float* b_row  = (const float*)d_in[4];
    const float* b_col  = (const float*)d_in[5];
    const float* b_ch   = (const float*)d_in[6];
    float* out = (float*)d_out;

    cudaFuncSetAttribute(wino_kernel,
                         cudaFuncAttributeMaxDynamicSharedMemorySize, SM_TOTAL);
    prep_cw_kernel<<<(HW + 255) / 256, 256>>>(cw_row, cw_col);
    prep_wU_kernel<<<128, 256>>>(w);
    wino_kernel<<<dim3(28, 32), 256, SM_TOTAL>>>(x, out, b_row, b_col, b_ch);
}

// round 17
// speedup vs baseline: 2.0646x; 1.0538x over previous
#include <cuda_runtime.h>
#include <cuda_fp16.h>
typedef unsigned int u32;

#define HH 56
#define WW 56
#define HW 3136

#define SM_CWS 64
#define SM_T   4096
#define SM_B   124928
#define SM_A   223232
#define SM_TOTAL 231936

__device__ __align__(16) u32   g_wU[64 * 8192];  // [stage][kp64][n128] fp16x2 swizzled
__device__ __align__(16) float g_cw[4 * HW];
__device__ const float CAF[2][4] = {{1.f, 1.f, 1.f, 0.f}, {0.f, 1.f, -1.f, -1.f}};

__device__ __forceinline__ u32 smem_u32(const void* p) {
    u32 a;
    asm("{ .reg .u64 t; cvta.to.shared.u64 t, %1; cvt.u32.u64 %0, t; }" : "=r"(a) : "l"(p));
    return a;
}
__device__ __forceinline__ u32 pack_h2(float lo, float hi) {
    __half2 h = __floats2half2_rn(lo, hi);
    return *(u32*)&h;
}
__device__ __forceinline__ void mbar_init(u32 a, u32 c) {
    asm volatile("mbarrier.init.shared.b64 [%0], %1;" :: "r"(a), "r"(c) : "memory");
}
__device__ __forceinline__ void mbar_expect_tx(u32 a, u32 b) {
    asm volatile("mbarrier.arrive.expect_tx.shared.b64 _, [%0], %1;" :: "r"(a), "r"(b) : "memory");
}
__device__ __forceinline__ void mbar_arrive(u32 a) {
    asm volatile("mbarrier.arrive.shared.b64 _, [%0];" :: "r"(a) : "memory");
}
__device__ __forceinline__ void mbar_wait(u32 a, int ph) {
    asm volatile(
        "{\n\t.reg .pred P;\n"
        "WL_%=:\n\t"
        "mbarrier.try_wait.parity.acquire.cta.shared::cta.b64 P, [%0], %1, 0x989680;\n\t"
        "@P bra.uni WD_%=;\n\t"
        "bra.uni WL_%=;\n\t"
        "WD_%=:\n\t}" :: "r"(a), "r"((u32)ph) : "memory");
}
__device__ __forceinline__ void bulk_copy(u32 d, const void* s, u32 b, u32 m) {
    asm volatile(
        "cp.async.bulk.shared::cluster.global.mbarrier::complete_tx::bytes [%0], [%1], %2, [%3];"
        :: "r"(d), "l"(s), "r"(b), "r"(m) : "memory");
}
__device__ __forceinline__ void mma_f16(float& d0, float& d1, float& d2, float& d3,
                                        u32 a0, u32 a1, u32 a2, u32 a3, u32 b0, u32 b1) {
    asm volatile(
        "mma.sync.aligned.m16n8k16.row.col.f32.f16.f16.f32 "
        "{%0,%1,%2,%3}, {%4,%5,%6,%7}, {%8,%9}, {%0,%1,%2,%3};"
        : "+f"(d0), "+f"(d1), "+f"(d2), "+f"(d3)
        : "r"(a0), "r"(a1), "r"(a2), "r"(a3), "r"(b0), "r"(b1));
}

__global__ void prep_cw_kernel(const float* __restrict__ cw_row,
                               const float* __restrict__ cw_col) {
    int idx = blockIdx.x * blockDim.x + threadIdx.x;
    if (idx >= HW) return;
    int y = idx / WW, x = idx % WW;
    float v0 = cw_row[y] + cw_col[x];
    float v1 = cw_row[HH + y] + cw_col[WW + x];
    float v2 = cw_row[2 * HH + y] + cw_col[2 * WW + x];
    float v3 = cw_row[3 * HH + y] + cw_col[3 * WW + x];
    float m = fmaxf(fmaxf(v0, v1), fmaxf(v2, v3));
    float e0 = expf(v0 - m), e1 = expf(v1 - m), e2 = expf(v2 - m), e3 = expf(v3 - m);
    float inv = 1.0f / (e0 + e1 + e2 + e3);
    g_cw[idx] = e0 * inv; g_cw[HW + idx] = e1 * inv;
    g_cw[2 * HW + idx] = e2 * inv; g_cw[3 * HW + idx] = e3 * inv;
}

__global__ void prep_wU_kernel(const float* __restrict__ w) {
    int idx = blockIdx.x * blockDim.x + threadIdx.x;
    if (idx >= 4 * 128 * 64) return;
    int kp = idx & 63, oc = (idx >> 6) & 127, r = idx >> 13;
    float U[2][4][4];
#pragma unroll
    for (int e2 = 0; e2 < 2; e2++) {
        const float* wb = w + (((size_t)r * 128 + oc) * 128 + 2 * kp + e2) * 9;
        float tm[4][3];
#pragma unroll
        for (int b = 0; b < 3; b++) {
            float w0 = wb[b], w1 = wb[3 + b], w2 = wb[6 + b];
            tm[0][b] = w0; tm[1][b] = 0.5f * (w0 + w1 + w2);
            tm[2][b] = 0.5f * (w0 - w1 + w2); tm[3][b] = w2;
        }
#pragma unroll
        for (int u = 0; u < 4; u++) {
            U[e2][u][0] = tm[u][0];
            U[e2][u][1] = 0.5f * (tm[u][0] + tm[u][1] + tm[u][2]);
            U[e2][u][2] = 0.5f * (tm[u][0] - tm[u][1] + tm[u][2]);
            U[e2][u][3] = tm[u][2];
        }
    }
    int col = oc ^ ((kp & 3) << 3);
#pragma unroll
    for (int u = 0; u < 4; u++)
#pragma unroll
        for (int v = 0; v < 4; v++)
            g_wU[(size_t)((u * 4 + v) * 4 + r) * 8192 + kp * 128 + col] =
                pack_h2(U[0][u][v], U[1][u][v]);
}

// Row transform: A_e rows 0..27 from fp32 T (single fp16 rounding). u = e>>2 slab.
__device__ __forceinline__ void buildA(u32* Ab, const float* T, int e, int tid) {
    int u = e >> 2, v = e & 3;
    const float* Tu = T + u * 58 * 130;
#pragma unroll
    for (int it = 0; it < 7; it++) {
        int idx = it * 256 + tid;
        int kp = idx & 63, b = idx >> 6;
        float2 p, q;
        if (v == 0)      { p = *(const float2*)&Tu[(2*b+0)*130+2*kp]; q = *(const float2*)&Tu[(2*b+2)*130+2*kp]; }
        else if (v == 1) { p = *(const float2*)&Tu[(2*b+1)*130+2*kp]; q = *(const float2*)&Tu[(2*b+2)*130+2*kp]; q.x = -q.x; q.y = -q.y; }
        else if (v == 2) { p = *(const float2*)&Tu[(2*b+2)*130+2*kp]; q = *(const float2*)&Tu[(2*b+1)*130+2*kp]; }
        else             { p = *(const float2*)&Tu[(2*b+1)*130+2*kp]; q = *(const float2*)&Tu[(2*b+3)*130+2*kp]; }
        Ab[b * 68 + kp] = pack_h2(p.x - q.x, p.y - q.y);
    }
}

// grid (28, 32) = (block-row y0, image). 256 thr = 8 warps (2 wm x 4 woc).
__global__ __launch_bounds__(256, 1)
void wino_kernel(const float* __restrict__ x, float* __restrict__ out,
                 const float* __restrict__ b_row, const float* __restrict__ b_col,
                 const float* __restrict__ b_ch) {
    extern __shared__ char smem[];
    const u32 sbase = smem_u32(smem);
    const int tid = threadIdx.x, wid = tid >> 5, lane = tid & 31;
    const int wm = wid & 1, woc = wid >> 1;
    const int g = lane >> 2, t = lane & 3;
    const int y0 = blockIdx.x, bb = blockIdx.y;

    float* cws = (float*)(smem + SM_CWS);
    float* T   = (float*)(smem + SM_T);
    u32*   Ab  = (u32*)(smem + SM_A);

    if (tid == 0) {
        for (int i = 0; i < 3; i++) mbar_init(sbase + i * 8, 1);        // full
        for (int i = 0; i < 3; i++) mbar_init(sbase + 24 + i * 8, 8);   // empty (8 warps)
    }
    __syncthreads();
    if (tid == 0)
        for (int i = 0; i < 3; i++) {
            mbar_expect_tx(sbase + i * 8, 32768);
            bulk_copy(sbase + SM_B + i * 32768, (const char*)g_wU + (size_t)i * 32768,
                      32768, sbase + i * 8);
        }

    // full T build (column transform B^T d), R11-identical
    {
        const float* xb = x + (size_t)bb * 128 * HW;
        for (int it = 0; it < 16; it++) {
            int idx = it * 256 + tid;
            int tx = idx & 63, kp = idx >> 6;
            if (tx < 58) {
                int gx = tx - 1;
                float d[4][2];
#pragma unroll
                for (int dy = 0; dy < 4; dy++) {
                    int gy = 2 * y0 - 1 + dy;
                    bool ok = (unsigned)gy < 56u && (unsigned)gx < 56u;
                    const float* s = xb + (size_t)(2 * kp) * HW + gy * WW + gx;
                    d[dy][0] = ok ? s[0] : 0.f;
                    d[dy][1] = ok ? s[HW] : 0.f;
                }
                float2 t0 = {d[0][0] - d[2][0], d[0][1] - d[2][1]};
                float2 t1 = {d[1][0] + d[2][0], d[1][1] + d[2][1]};
                float2 t2 = {d[2][0] - d[1][0], d[2][1] - d[1][1]};
                float2 t3 = {d[1][0] - d[3][0], d[1][1] - d[3][1]};
                *(float2*)&T[(0 * 58 + tx) * 130 + 2 * kp] = t0;
                *(float2*)&T[(1 * 58 + tx) * 130 + 2 * kp] = t1;
                *(float2*)&T[(2 * 58 + tx) * 130 + 2 * kp] = t2;
                *(float2*)&T[(3 * 58 + tx) * 130 + 2 * kp] = t3;
            }
        }
    }
    for (int idx = tid; idx < 448; idx += 256) {
        int rr = idx / 112, rem = idx % 112;
        cws[idx] = g_cw[rr * HW + (2 * y0 + rem / 56) * 56 + rem % 56];
    }
    for (int i = 28 * 68 + tid; i < 32 * 68; i += 256) Ab[i] = 0;
    __syncthreads();
    buildA(Ab, T, 0, tid);
    __syncthreads();

    float acc[2][2][4][4];
#pragma unroll
    for (int i = 0; i < 2; i++)
#pragma unroll
        for (int j = 0; j < 2; j++)
#pragma unroll
            for (int nt = 0; nt < 4; nt++)
#pragma unroll
                for (int v2 = 0; v2 < 4; v2++) acc[i][j][nt][v2] = 0.f;

    const int ar0 = (wm * 16 + g) * 68, ar1 = ar0 + 8 * 68;

    for (int s = 0; s < 64; s++) {
        const int e = s >> 2, r = s & 3, u = e >> 2, v = e & 3;
        const int buf = s % 3, ph = (s / 3) & 1;

        mbar_wait(sbase + buf * 8, ph);

        float mf[4][4];
#pragma unroll
        for (int nt = 0; nt < 4; nt++)
#pragma unroll
            for (int v2 = 0; v2 < 4; v2++) mf[nt][v2] = 0.f;

        const u32* Bb = (const u32*)(smem + SM_B + buf * 32768);
#pragma unroll
        for (int ks = 0; ks < 8; ks++) {
            const int ak = ks * 8 + t;
            u32 a0 = Ab[ar0 + ak], a1 = Ab[ar1 + ak];
            u32 a2 = Ab[ar0 + ak + 4], a3 = Ab[ar1 + ak + 4];
#pragma unroll
            for (int nt = 0; nt < 4; nt++) {
                const int col = (woc * 32 + nt * 8 + g) ^ (t << 3);
                mma_f16(mf[nt][0], mf[nt][1], mf[nt][2], mf[nt][3],
                        a0, a1, a2, a3, Bb[ak * 128 + col], Bb[(ak + 4) * 128 + col]);
            }
        }

        // release this B buffer (per-warp arrive; no block-wide barrier)
        __syncwarp();
        if (lane == 0) mbar_arrive(sbase + 24 + buf * 8);

        // fold: acc += A^T[i][u]*A^T[j][v]*cw_r(px) * mf
        {
            const float cu0 = CAF[0][u], cu1 = CAF[1][u];
            const float cv0 = CAF[0][v], cv1 = CAF[1][v];
#pragma unroll
            for (int i = 0; i < 2; i++)
#pragma unroll
                for (int j = 0; j < 2; j++) {
                    const float ca = (i ? cu1 : cu0) * (j ? cv1 : cv0);
                    if (ca != 0.f) {
                        const float w0 = ca * cws[r * 112 + i * 56 + 2 * (wm * 16 + g) + j];
                        const float w1 = ca * cws[r * 112 + i * 56 + 2 * (wm * 16 + g + 8) + j];
#pragma unroll
                        for (int nt = 0; nt < 4; nt++) {
                            acc[i][j][nt][0] += w0 * mf[nt][0];
                            acc[i][j][nt][1] += w0 * mf[nt][1];
                            acc[i][j][nt][2] += w1 * mf[nt][2];
                            acc[i][j][nt][3] += w1 * mf[nt][3];
                        }
                    }
                }
        }

        // tid0: wait all 8 warps released buf, then refill it for stage s+3
        if (tid == 0 && s + 3 < 64) {
            mbar_wait(sbase + 24 + buf * 8, ph);
            mbar_expect_tx(sbase + buf * 8, 32768);
            bulk_copy(sbase + SM_B + buf * 32768,
                      (const char*)g_wU + (size_t)(s + 3) * 32768, 32768,
                      sbase + buf * 8);
        }

        if (r == 3 && s < 63) {
            __syncthreads();
            buildA(Ab, T, e + 1, tid);
            __syncthreads();
        }
    }

    // epilogue: direct stores + biases (R11-identical)
    const float br0 = b_row[2 * y0], br1 = b_row[2 * y0 + 1];
#pragma unroll
    for (int i = 0; i < 2; i++)
#pragma unroll
        for (int j = 0; j < 2; j++)
#pragma unroll
            for (int nt = 0; nt < 4; nt++)
#pragma unroll
                for (int v2 = 0; v2 < 4; v2++) {
                    const int b = wm * 16 + g + 8 * (v2 >> 1);
                    if (b < 28) {
                        const int xx = 2 * b + j, yy = 2 * y0 + i;
                        const int oc = woc * 32 + nt * 8 + 2 * t + (v2 & 1);
                        out[((size_t)(bb * 128 + oc) * 56 + yy) * 56 + xx] =
                            acc[i][j][nt][v2] + (i ? br1 : br0) + b_col[xx] + b_ch[oc];
                    }
                }
}

extern "C" void kernel_launch(void* const* d_in, const int* in_sizes, int n_in,
                              void* d_out, int out_size) {
    const float* x      = (const float*)d_in[0];
    const float* w      = (const float*)d_in[1];
    const float* cw_row = (const float*)d_in[2];
    const float* cw_col = (const float*)d_in[3];
    const float* b_row  = (const float*)d_in[4];
    const float* b_col  = (const float*)d_in[5];
    const float* b_ch   = (const float*)d_in[6];
    float* out = (float*)d_out;

    cudaFuncSetAttribute(wino_kernel,
                         cudaFuncAttributeMaxDynamicSharedMemorySize, SM_TOTAL);
    prep_cw_kernel<<<(HW + 255) / 256, 256>>>(cw_row, cw_col);
    prep_wU_kernel<<<128, 256>>>(w);
    wino_kernel<<<dim3(28, 32), 256, SM_TOTAL>>>(x, out, b_row, b_col, b_ch);
}